// round 16
// baseline (speedup 1.0000x reference)
#include <cuda_runtime.h>
#include <cuda_fp16.h>
#include <math.h>

#define NN   8192
#define EE   4096
#define VH   128
#define H0   64
#define COL_CAP 192
#define ROW_CAP 112
#define BN_EPS 1e-5f
#define BN_SLOTS 8
#define FULL 0xFFFFFFFFu
#define GEMM_BLKS 512
#define SCAN_BLKS 8192         // 65536 warp-tasks x 512 elems = 32M elements
#define TNB  296               // tail kernel blocks (148 SMs x 2, co-resident)
#define TNW  (TNB * 8)         // tail warps

// -------- device scratch (zero-init at module load; tail restores zeros) --
__device__ int   g_col_cnt[EE];
__device__ int   g_row_cnt[NN];
__device__ int   g_col_idx[EE * COL_CAP];
__device__ int   g_row_idx[NN * ROW_CAP];
__device__ __align__(16) __half g_Z1h[NN * H0];
__device__ __align__(16) __half g_M1h[EE * H0];
__device__ __align__(16) __half g_X1h[NN * H0];
__device__ float g_bn_sum[BN_SLOTS * H0];
__device__ float g_bn_sq [BN_SLOTS * H0];
__device__ float g_WDe[EE];
__device__ float g_Z2[NN];
__device__ float g_M2[EE];
__device__ int   g_bar_cnt[4];
__device__ int   g_bar_epoch[4];

// grid-wide epoch barrier (validated R4 pattern); safe across graph replays
__device__ __forceinline__ void grid_barrier(int slot) {
    __syncthreads();
    if (threadIdx.x == 0) {
        int* ep = &g_bar_epoch[slot];
        int* cp = &g_bar_cnt[slot];
        int e;
        asm volatile("ld.acquire.gpu.global.b32 %0, [%1];" : "=r"(e) : "l"(ep) : "memory");
        int prev;
        asm volatile("atom.release.gpu.global.add.s32 %0, [%1], %2;"
                     : "=r"(prev) : "l"(cp), "r"(1) : "memory");
        if (prev == TNB - 1) {
            asm volatile("st.relaxed.gpu.global.b32 [%0], %1;" :: "l"(cp), "r"(0) : "memory");
            asm volatile("red.release.gpu.global.add.s32 [%0], %1;" :: "l"(ep), "r"(1) : "memory");
        } else {
            int cur;
            do {
                __nanosleep(32);
                asm volatile("ld.acquire.gpu.global.b32 %0, [%1];" : "=r"(cur) : "l"(ep) : "memory");
            } while (cur == e);
        }
    }
    __syncthreads();
}

__device__ __forceinline__ void acc8(float* a, int4 v) {
    half2* h = reinterpret_cast<half2*>(&v);
    #pragma unroll
    for (int j = 0; j < 4; j++) {
        float2 f = __half22float2(h[j]);
        a[2*j]   += f.x;
        a[2*j+1] += f.y;
    }
}

__device__ __forceinline__ void accp(float* a, int4 u, int4 v) {
    half2* hu = reinterpret_cast<half2*>(&u);
    half2* hv = reinterpret_cast<half2*>(&v);
    #pragma unroll
    for (int j = 0; j < 4; j++) {
        float2 f = __half22float2(__hadd2(hu[j], hv[j]));
        a[2*j]   += f.x;
        a[2*j+1] += f.y;
    }
}

// ---------------------------------------------------------------------------
// kAB: bid<GEMM_BLKS: Z1 = Dv*(X@theta1) + WDe ; else: dense-H scan -> ELL
__global__ void __launch_bounds__(256)
kAB(const float* __restrict__ X,  const float* __restrict__ th1,
    const float* __restrict__ Dv, const float* __restrict__ Hm,
    const float* __restrict__ W,  const float* __restrict__ De) {
    __shared__ float xs[16 * VH];
    int tid = threadIdx.x, bid = blockIdx.x;
    int lane = tid & 31, warp = tid >> 5;

    if (bid < GEMM_BLKS) {
        int t = bid * 256 + tid;
        if (t < EE) g_WDe[t] = W[t] * De[t];
        const float4* X4 = reinterpret_cast<const float4*>(X + bid * 16 * VH);
        float4* xs4 = reinterpret_cast<float4*>(xs);
        xs4[tid]       = X4[tid];
        xs4[tid + 256] = X4[tid + 256];
        __syncthreads();
        int h = tid & 63, grp = tid >> 6;
        const float* xr = xs + grp * 4 * VH;
        float a0 = 0, a1 = 0, a2 = 0, a3 = 0;
        #pragma unroll 8
        for (int k = 0; k < VH; k++) {
            float tv = __ldg(&th1[k * H0 + h]);
            a0 += xr[k]          * tv;
            a1 += xr[VH + k]     * tv;
            a2 += xr[2 * VH + k] * tv;
            a3 += xr[3 * VH + k] * tv;
        }
        int n0 = bid * 16 + grp * 4;
        g_Z1h[(n0 + 0) * H0 + h] = __float2half(a0 * __ldg(&Dv[n0 + 0]));
        g_Z1h[(n0 + 1) * H0 + h] = __float2half(a1 * __ldg(&Dv[n0 + 1]));
        g_Z1h[(n0 + 2) * H0 + h] = __float2half(a2 * __ldg(&Dv[n0 + 2]));
        g_Z1h[(n0 + 3) * H0 + h] = __float2half(a3 * __ldg(&Dv[n0 + 3]));
        return;
    }

    // ---- scan family: 512 elements per warp ----
    unsigned wt = (unsigned)(bid - GEMM_BLKS) * 8u + (unsigned)warp;
    const float4* H4 = reinterpret_cast<const float4*>(Hm);
    unsigned f0 = wt * 128u + (unsigned)lane;
    float4 v0 = __ldcs(&H4[f0]);
    float4 v1 = __ldcs(&H4[f0 + 32]);
    float4 v2 = __ldcs(&H4[f0 + 64]);
    float4 v3 = __ldcs(&H4[f0 + 96]);
    unsigned ebase = wt * 512u;
    int n = (int)(ebase >> 12);            // 512 | 4096 -> single row per warp
    float vals[16] = {v0.x, v0.y, v0.z, v0.w,  v1.x, v1.y, v1.z, v1.w,
                      v2.x, v2.y, v2.z, v2.w,  v3.x, v3.y, v3.z, v3.w};
    int nz = 0;
    #pragma unroll
    for (int j = 0; j < 16; j++) nz += (vals[j] != 0.0f);
    int pre = nz;
    #pragma unroll
    for (int d = 1; d < 32; d <<= 1) {
        int u = __shfl_up_sync(FULL, pre, d);
        if (lane >= d) pre += u;
    }
    int tot = __shfl_sync(FULL, pre, 31);
    if (tot == 0) return;
    int rbase = 0;
    if (lane == 31) rbase = atomicAdd(&g_row_cnt[n], tot);
    rbase = __shfl_sync(FULL, rbase, 31);
    int q = rbase + (pre - nz);
    unsigned e0a = (ebase & 4095u) + (unsigned)lane * 4u;
    #pragma unroll
    for (int j = 0; j < 16; j++) {
        if (vals[j] != 0.0f) {
            int e = (int)(e0a + (unsigned)(j >> 2) * 128u + (unsigned)(j & 3));
            if (q < ROW_CAP) g_row_idx[n * ROW_CAP + q] = e;
            q++;
            int p = atomicAdd(&g_col_cnt[e], 1);
            if (p < COL_CAP) g_col_idx[e * COL_CAP + p] = n;
        }
    }
}

// ---------------------------------------------------------------------------
// kC: M1[e,:] = WDe[e] * col-gather(Z1)   (2-warp teams, 4 edges / block)
__global__ void __launch_bounds__(256) kC_edge() {
    __shared__ int   sl[4][COL_CAP];
    __shared__ float sp[4][64];
    int tid = threadIdx.x;
    int warp = tid >> 5, lane = tid & 31;
    int team = warp >> 1, sub = warp & 1;
    int e = blockIdx.x * 4 + team;
    int cnt = min(g_col_cnt[e], COL_CAP);
    const int* lst = &g_col_idx[e * COL_CAP];
    int tt = tid & 63;
    for (int i = tt; i < cnt; i += 64) sl[team][i] = lst[i];
    __syncthreads();

    int rg = lane >> 3, cg = lane & 7;
    float a[8] = {0,0,0,0,0,0,0,0};
    const int4* Z = reinterpret_cast<const int4*>(g_Z1h);
    int nfull = cnt >> 4;
    for (int k = sub; k < nfull; k += 2) {
        int i = k << 4;
        int m0 = sl[team][i + rg],     m1 = sl[team][i + 4 + rg];
        int m2 = sl[team][i + 8 + rg], m3 = sl[team][i + 12 + rg];
        int4 w0 = __ldg(&Z[m0 * 8 + cg]);
        int4 w1 = __ldg(&Z[m1 * 8 + cg]);
        int4 w2 = __ldg(&Z[m2 * 8 + cg]);
        int4 w3 = __ldg(&Z[m3 * 8 + cg]);
        accp(a, w0, w1);
        accp(a, w2, w3);
    }
    if (sub == (nfull & 1)) {
        int i = nfull << 4;
        for (; i + 4 <= cnt; i += 4)
            acc8(a, __ldg(&Z[sl[team][i + rg] * 8 + cg]));
        if (i + rg < cnt)
            acc8(a, __ldg(&Z[sl[team][i + rg] * 8 + cg]));
    }
    #pragma unroll
    for (int c = 0; c < 8; c++) {
        a[c] += __shfl_xor_sync(FULL, a[c], 8);
        a[c] += __shfl_xor_sync(FULL, a[c], 16);
    }
    if (sub == 1 && rg == 0) {
        #pragma unroll
        for (int c = 0; c < 8; c++) sp[team][cg * 8 + c] = a[c];
    }
    __syncthreads();
    if (sub == 0 && rg == 0) {
        float s = g_WDe[e];
        #pragma unroll
        for (int c = 0; c < 8; c++) a[c] = (a[c] + sp[team][cg * 8 + c]) * s;
        half2 h0 = __floats2half2_rn(a[0], a[1]);
        half2 h1 = __floats2half2_rn(a[2], a[3]);
        half2 h2 = __floats2half2_rn(a[4], a[5]);
        half2 h3 = __floats2half2_rn(a[6], a[7]);
        int4 ov;
        ov.x = *reinterpret_cast<int*>(&h0);
        ov.y = *reinterpret_cast<int*>(&h1);
        ov.z = *reinterpret_cast<int*>(&h2);
        ov.w = *reinterpret_cast<int*>(&h3);
        reinterpret_cast<int4*>(g_M1h)[e * 8 + cg] = ov;
    }
}

// ---------------------------------------------------------------------------
// kD: X1 = leaky_relu(Dv * row-gather(M1)) + BN partials  (warp per node)
__global__ void __launch_bounds__(256) kD_node(const float* __restrict__ Dv) {
    __shared__ int sl[8][ROW_CAP];
    __shared__ float bs[H0], bq[H0];
    int warp = threadIdx.x >> 5, lane = threadIdx.x & 31;
    if (threadIdx.x < H0) { bs[threadIdx.x] = 0.0f; bq[threadIdx.x] = 0.0f; }
    __syncthreads();

    int n = blockIdx.x * 8 + warp;
    int cnt = min(g_row_cnt[n], ROW_CAP);
    const int* lst = &g_row_idx[n * ROW_CAP];
    for (int i = lane; i < cnt; i += 32) sl[warp][i] = lst[i];
    __syncwarp();

    int rg = lane >> 3, cg = lane & 7;
    float a[8] = {0,0,0,0,0,0,0,0};
    const int4* M = reinterpret_cast<const int4*>(g_M1h);
    int i = 0;
    for (; i + 16 <= cnt; i += 16) {
        int m0 = sl[warp][i + rg],     m1 = sl[warp][i + 4 + rg];
        int m2 = sl[warp][i + 8 + rg], m3 = sl[warp][i + 12 + rg];
        int4 w0 = __ldg(&M[m0 * 8 + cg]);
        int4 w1 = __ldg(&M[m1 * 8 + cg]);
        int4 w2 = __ldg(&M[m2 * 8 + cg]);
        int4 w3 = __ldg(&M[m3 * 8 + cg]);
        accp(a, w0, w1);
        accp(a, w2, w3);
    }
    for (; i + 4 <= cnt; i += 4)
        acc8(a, __ldg(&M[sl[warp][i + rg] * 8 + cg]));
    if (i + rg < cnt)
        acc8(a, __ldg(&M[sl[warp][i + rg] * 8 + cg]));
    #pragma unroll
    for (int c = 0; c < 8; c++) {
        a[c] += __shfl_xor_sync(FULL, a[c], 8);
        a[c] += __shfl_xor_sync(FULL, a[c], 16);
    }
    if (rg == 0) {
        float dv = __ldg(&Dv[n]);
        #pragma unroll
        for (int c = 0; c < 8; c++) {
            float xbar = a[c] * dv;
            float x1 = xbar > 0.0f ? xbar : 0.01f * xbar;
            a[c] = x1;
            atomicAdd(&bs[cg * 8 + c], x1);
            atomicAdd(&bq[cg * 8 + c], x1 * x1);
        }
        half2 oh0 = __floats2half2_rn(a[0], a[1]);
        half2 oh1 = __floats2half2_rn(a[2], a[3]);
        half2 oh2 = __floats2half2_rn(a[4], a[5]);
        half2 oh3 = __floats2half2_rn(a[6], a[7]);
        int4 ov;
        ov.x = *reinterpret_cast<int*>(&oh0);
        ov.y = *reinterpret_cast<int*>(&oh1);
        ov.z = *reinterpret_cast<int*>(&oh2);
        ov.w = *reinterpret_cast<int*>(&oh3);
        reinterpret_cast<int4*>(g_X1h)[n * 8 + cg] = ov;
    }
    __syncthreads();
    if (threadIdx.x < H0) {
        int slot = (blockIdx.x & (BN_SLOTS - 1)) * H0 + threadIdx.x;
        atomicAdd(&g_bn_sum[slot], bs[threadIdx.x]);
        atomicAdd(&g_bn_sq[slot],  bq[threadIdx.x]);
    }
}

// ---------------------------------------------------------------------------
// kEFG: persistent tail. Phase E: BN finalize + Z2; barrier; Phase F: M2
// edge-gather; barrier; Phase G: output node-gather + restore zero-invariants.
__global__ void __launch_bounds__(256)
kEFG(const float* __restrict__ gamma, const float* __restrict__ beta,
     const float* __restrict__ th2,   const float* __restrict__ Dv,
     float* __restrict__ out) {
    __shared__ float scoef[H0];
    __shared__ float sred[H0];
    __shared__ float sc0s;
    int t = threadIdx.x;
    int warp = t >> 5, lane = t & 31;
    int gw = blockIdx.x * 8 + warp;
    int gt = blockIdx.x * 256 + t;

    // ---- Phase E: BN finalize (per block) + Z2 over strided nodes ----
    if (t < H0) {
        float s = 0.0f, q = 0.0f;
        #pragma unroll
        for (int j = 0; j < BN_SLOTS; j++) {
            s += g_bn_sum[j * H0 + t];
            q += g_bn_sq [j * H0 + t];
        }
        float mu   = s * (1.0f / NN);
        float var  = q * (1.0f / NN) - mu * mu;
        float rstd = rsqrtf(var + BN_EPS);
        float scale = rstd * __ldg(&gamma[t]);
        float shift = __ldg(&beta[t]) - mu * scale;
        float th = __ldg(&th2[t]);
        scoef[t] = scale * th;
        sred[t]  = shift * th;
    }
    __syncthreads();
    if (warp == 0) {
        float r = sred[lane] + sred[lane + 32];
        #pragma unroll
        for (int off = 16; off > 0; off >>= 1)
            r += __shfl_xor_sync(FULL, r, off);
        if (lane == 0) sc0s = r;
    }
    __syncthreads();
    float sc0 = sc0s;
    {
        const half2*  Xh = reinterpret_cast<const half2*>(g_X1h);
        const float2* C2 = reinterpret_cast<const float2*>(scoef);
        float2 c = C2[lane];
        for (int n = gw; n < NN; n += TNW) {
            float2 x = __half22float2(Xh[n * 32 + lane]);
            float v = x.x * c.x + x.y * c.y;
            #pragma unroll
            for (int off = 16; off > 0; off >>= 1)
                v += __shfl_xor_sync(FULL, v, off);
            if (lane == 0) g_Z2[n] = __ldg(&Dv[n]) * (v + sc0);
        }
    }
    grid_barrier(0);

    // ---- Phase F: M2[e] = WDe[e] * col-gather(Z2) ----
    for (int e = gw; e < EE; e += TNW) {
        int cnt = min(g_col_cnt[e], COL_CAP);
        const int* lst = &g_col_idx[e * COL_CAP];
        float a = 0.0f;
        for (int i = lane; i < cnt; i += 32) a += g_Z2[__ldg(&lst[i])];
        #pragma unroll
        for (int off = 16; off > 0; off >>= 1)
            a += __shfl_xor_sync(FULL, a, off);
        if (lane == 0) g_M2[e] = a * g_WDe[e];
    }
    grid_barrier(1);

    // ---- Phase G: out + restore zero-invariants ----
    if (gt < EE) g_col_cnt[gt] = 0;
    if (gt < BN_SLOTS * H0) { g_bn_sum[gt] = 0.0f; g_bn_sq[gt] = 0.0f; }
    for (int n = gw; n < NN; n += TNW) {
        int cnt = min(g_row_cnt[n], ROW_CAP);
        const int* lst = &g_row_idx[n * ROW_CAP];
        float a = 0.0f;
        for (int i = lane; i < cnt; i += 32) a += g_M2[__ldg(&lst[i])];
        #pragma unroll
        for (int off = 16; off > 0; off >>= 1)
            a += __shfl_xor_sync(FULL, a, off);
        if (lane == 0) {
            float x = __ldg(&Dv[n]) * a;
            out[n] = 1.0f / (1.0f + __expf(-x));
            g_row_cnt[n] = 0;
        }
    }
}

extern "C" void kernel_launch(void* const* d_in, const int* in_sizes, int n_in,
                              void* d_out, int out_size) {
    const float* X     = (const float*)d_in[0];
    const float* Dv    = (const float*)d_in[1];
    const float* De    = (const float*)d_in[2];
    const float* Hm    = (const float*)d_in[3];
    const float* W     = (const float*)d_in[4];
    const float* th1   = (const float*)d_in[5];
    const float* th2   = (const float*)d_in[6];
    const float* gamma = (const float*)d_in[7];
    const float* beta  = (const float*)d_in[8];
    float* out = (float*)d_out;

    kAB<<<GEMM_BLKS + SCAN_BLKS, 256>>>(X, th1, Dv, Hm, W, De);
    kC_edge<<<EE / 4, 256>>>();
    kD_node<<<NN / 8, 256>>>(Dv);
    kEFG   <<<TNB, 256>>>(gamma, beta, th2, Dv, out);
}

// round 17
// speedup vs baseline: 1.1763x; 1.1763x over previous
#include <cuda_runtime.h>
#include <cuda_fp16.h>
#include <math.h>

#define NN   8192
#define EE   4096
#define VH   128
#define H0   64
#define COL_CAP 192
#define ROW_CAP 112
#define BN_EPS 1e-5f
#define BN_SLOTS 8
#define FULL 0xFFFFFFFFu
#define GEMM_BLKS 512
#define SCAN_BLKS 8192         // 65536 warp-tasks x 512 elems = 32M elements

// -------- device scratch (zero-init at module load; kG restores zeros) ----
__device__ int   g_col_cnt[EE];
__device__ int   g_row_cnt[NN];
__device__ int   g_col_idx[EE * COL_CAP];
__device__ int   g_row_idx[NN * ROW_CAP];
__device__ __align__(16) __half g_Z1h[NN * H0];
__device__ __align__(16) __half g_M1h[EE * H0];
__device__ __align__(16) __half g_X1h[NN * H0];
__device__ float g_bn_sum[BN_SLOTS * H0];
__device__ float g_bn_sq [BN_SLOTS * H0];
__device__ float g_WDe[EE];
__device__ float g_Z2[NN];
__device__ float g_M2[EE];

__device__ __forceinline__ void acc8(float* a, int4 v) {
    half2* h = reinterpret_cast<half2*>(&v);
    #pragma unroll
    for (int j = 0; j < 4; j++) {
        float2 f = __half22float2(h[j]);
        a[2*j]   += f.x;
        a[2*j+1] += f.y;
    }
}

__device__ __forceinline__ void accp(float* a, int4 u, int4 v) {
    half2* hu = reinterpret_cast<half2*>(&u);
    half2* hv = reinterpret_cast<half2*>(&v);
    #pragma unroll
    for (int j = 0; j < 4; j++) {
        float2 f = __half22float2(__hadd2(hu[j], hv[j]));
        a[2*j]   += f.x;
        a[2*j+1] += f.y;
    }
}

// ---------------------------------------------------------------------------
// kAB: bid<GEMM_BLKS: Z1 = Dv*(X@theta1) + WDe ; else: dense-H scan -> ELL
// Scan: 512 elems/warp (4x512B loads up-front), single warp-scan, ONE row
// atomic, and a bitmask-driven epilogue (iterate only over nonzeros).
__global__ void __launch_bounds__(256)
kAB(const float* __restrict__ X,  const float* __restrict__ th1,
    const float* __restrict__ Dv, const float* __restrict__ Hm,
    const float* __restrict__ W,  const float* __restrict__ De) {
    __shared__ float xs[16 * VH];
    int tid = threadIdx.x, bid = blockIdx.x;
    int lane = tid & 31, warp = tid >> 5;

    if (bid < GEMM_BLKS) {
        int t = bid * 256 + tid;
        if (t < EE) g_WDe[t] = W[t] * De[t];
        const float4* X4 = reinterpret_cast<const float4*>(X + bid * 16 * VH);
        float4* xs4 = reinterpret_cast<float4*>(xs);
        xs4[tid]       = X4[tid];
        xs4[tid + 256] = X4[tid + 256];
        __syncthreads();
        int h = tid & 63, grp = tid >> 6;
        const float* xr = xs + grp * 4 * VH;
        float a0 = 0, a1 = 0, a2 = 0, a3 = 0;
        #pragma unroll 8
        for (int k = 0; k < VH; k++) {
            float tv = __ldg(&th1[k * H0 + h]);
            a0 += xr[k]          * tv;
            a1 += xr[VH + k]     * tv;
            a2 += xr[2 * VH + k] * tv;
            a3 += xr[3 * VH + k] * tv;
        }
        int n0 = bid * 16 + grp * 4;
        g_Z1h[(n0 + 0) * H0 + h] = __float2half(a0 * __ldg(&Dv[n0 + 0]));
        g_Z1h[(n0 + 1) * H0 + h] = __float2half(a1 * __ldg(&Dv[n0 + 1]));
        g_Z1h[(n0 + 2) * H0 + h] = __float2half(a2 * __ldg(&Dv[n0 + 2]));
        g_Z1h[(n0 + 3) * H0 + h] = __float2half(a3 * __ldg(&Dv[n0 + 3]));
        return;
    }

    // ---- scan family: 512 elements per warp ----
    unsigned wt = (unsigned)(bid - GEMM_BLKS) * 8u + (unsigned)warp;
    const float4* H4 = reinterpret_cast<const float4*>(Hm);
    unsigned f0 = wt * 128u + (unsigned)lane;
    float4 v0 = __ldcs(&H4[f0]);
    float4 v1 = __ldcs(&H4[f0 + 32]);
    float4 v2 = __ldcs(&H4[f0 + 64]);
    float4 v3 = __ldcs(&H4[f0 + 96]);
    unsigned ebase = wt * 512u;
    int n = (int)(ebase >> 12);            // 512 | 4096 -> single row per warp
    float vals[16] = {v0.x, v0.y, v0.z, v0.w,  v1.x, v1.y, v1.z, v1.w,
                      v2.x, v2.y, v2.z, v2.w,  v3.x, v3.y, v3.z, v3.w};
    unsigned mask = 0;
    #pragma unroll
    for (int j = 0; j < 16; j++)
        if (vals[j] != 0.0f) mask |= (1u << j);
    int nz = __popc(mask);
    int pre = nz;
    #pragma unroll
    for (int d = 1; d < 32; d <<= 1) {
        int u = __shfl_up_sync(FULL, pre, d);
        if (lane >= d) pre += u;
    }
    int tot = __shfl_sync(FULL, pre, 31);
    if (tot == 0) return;
    int rbase = 0;
    if (lane == 31) rbase = atomicAdd(&g_row_cnt[n], tot);
    rbase = __shfl_sync(FULL, rbase, 31);
    int q = rbase + (pre - nz);
    unsigned e0a = (ebase & 4095u) + (unsigned)lane * 4u;
    while (mask) {
        int j = __ffs(mask) - 1;
        mask &= mask - 1;
        int e = (int)(e0a + (unsigned)(j >> 2) * 128u + (unsigned)(j & 3));
        if (q < ROW_CAP) g_row_idx[n * ROW_CAP + q] = e;
        q++;
        int p = atomicAdd(&g_col_cnt[e], 1);
        if (p < COL_CAP) g_col_idx[e * COL_CAP + p] = n;
    }
}

// ---------------------------------------------------------------------------
// kC: M1[e,:] = WDe[e] * col-gather(Z1)   (2-warp teams, 4 edges / block)
__global__ void __launch_bounds__(256) kC_edge() {
    __shared__ int   sl[4][COL_CAP];
    __shared__ float sp[4][64];
    int tid = threadIdx.x;
    int warp = tid >> 5, lane = tid & 31;
    int team = warp >> 1, sub = warp & 1;
    int e = blockIdx.x * 4 + team;
    int cnt = min(g_col_cnt[e], COL_CAP);
    const int* lst = &g_col_idx[e * COL_CAP];
    int tt = tid & 63;
    for (int i = tt; i < cnt; i += 64) sl[team][i] = lst[i];
    __syncthreads();

    int rg = lane >> 3, cg = lane & 7;
    float a[8] = {0,0,0,0,0,0,0,0};
    const int4* Z = reinterpret_cast<const int4*>(g_Z1h);
    int nfull = cnt >> 4;
    for (int k = sub; k < nfull; k += 2) {
        int i = k << 4;
        int m0 = sl[team][i + rg],     m1 = sl[team][i + 4 + rg];
        int m2 = sl[team][i + 8 + rg], m3 = sl[team][i + 12 + rg];
        int4 w0 = __ldg(&Z[m0 * 8 + cg]);
        int4 w1 = __ldg(&Z[m1 * 8 + cg]);
        int4 w2 = __ldg(&Z[m2 * 8 + cg]);
        int4 w3 = __ldg(&Z[m3 * 8 + cg]);
        accp(a, w0, w1);
        accp(a, w2, w3);
    }
    if (sub == (nfull & 1)) {
        int i = nfull << 4;
        for (; i + 4 <= cnt; i += 4)
            acc8(a, __ldg(&Z[sl[team][i + rg] * 8 + cg]));
        if (i + rg < cnt)
            acc8(a, __ldg(&Z[sl[team][i + rg] * 8 + cg]));
    }
    #pragma unroll
    for (int c = 0; c < 8; c++) {
        a[c] += __shfl_xor_sync(FULL, a[c], 8);
        a[c] += __shfl_xor_sync(FULL, a[c], 16);
    }
    if (sub == 1 && rg == 0) {
        #pragma unroll
        for (int c = 0; c < 8; c++) sp[team][cg * 8 + c] = a[c];
    }
    __syncthreads();
    if (sub == 0 && rg == 0) {
        float s = g_WDe[e];
        #pragma unroll
        for (int c = 0; c < 8; c++) a[c] = (a[c] + sp[team][cg * 8 + c]) * s;
        half2 h0 = __floats2half2_rn(a[0], a[1]);
        half2 h1 = __floats2half2_rn(a[2], a[3]);
        half2 h2 = __floats2half2_rn(a[4], a[5]);
        half2 h3 = __floats2half2_rn(a[6], a[7]);
        int4 ov;
        ov.x = *reinterpret_cast<int*>(&h0);
        ov.y = *reinterpret_cast<int*>(&h1);
        ov.z = *reinterpret_cast<int*>(&h2);
        ov.w = *reinterpret_cast<int*>(&h3);
        reinterpret_cast<int4*>(g_M1h)[e * 8 + cg] = ov;
    }
}

// ---------------------------------------------------------------------------
// kD: X1 = leaky_relu(Dv * row-gather(M1)) + BN partials  (warp per node)
__global__ void __launch_bounds__(256) kD_node(const float* __restrict__ Dv) {
    __shared__ int sl[8][ROW_CAP];
    __shared__ float bs[H0], bq[H0];
    int warp = threadIdx.x >> 5, lane = threadIdx.x & 31;
    if (threadIdx.x < H0) { bs[threadIdx.x] = 0.0f; bq[threadIdx.x] = 0.0f; }
    __syncthreads();

    int n = blockIdx.x * 8 + warp;
    int cnt = min(g_row_cnt[n], ROW_CAP);
    const int* lst = &g_row_idx[n * ROW_CAP];
    for (int i = lane; i < cnt; i += 32) sl[warp][i] = lst[i];
    __syncwarp();

    int rg = lane >> 3, cg = lane & 7;
    float a[8] = {0,0,0,0,0,0,0,0};
    const int4* M = reinterpret_cast<const int4*>(g_M1h);
    int i = 0;
    for (; i + 16 <= cnt; i += 16) {
        int m0 = sl[warp][i + rg],     m1 = sl[warp][i + 4 + rg];
        int m2 = sl[warp][i + 8 + rg], m3 = sl[warp][i + 12 + rg];
        int4 w0 = __ldg(&M[m0 * 8 + cg]);
        int4 w1 = __ldg(&M[m1 * 8 + cg]);
        int4 w2 = __ldg(&M[m2 * 8 + cg]);
        int4 w3 = __ldg(&M[m3 * 8 + cg]);
        accp(a, w0, w1);
        accp(a, w2, w3);
    }
    for (; i + 4 <= cnt; i += 4)
        acc8(a, __ldg(&M[sl[warp][i + rg] * 8 + cg]));
    if (i + rg < cnt)
        acc8(a, __ldg(&M[sl[warp][i + rg] * 8 + cg]));
    #pragma unroll
    for (int c = 0; c < 8; c++) {
        a[c] += __shfl_xor_sync(FULL, a[c], 8);
        a[c] += __shfl_xor_sync(FULL, a[c], 16);
    }
    if (rg == 0) {
        float dv = __ldg(&Dv[n]);
        #pragma unroll
        for (int c = 0; c < 8; c++) {
            float xbar = a[c] * dv;
            float x1 = xbar > 0.0f ? xbar : 0.01f * xbar;
            a[c] = x1;
            atomicAdd(&bs[cg * 8 + c], x1);
            atomicAdd(&bq[cg * 8 + c], x1 * x1);
        }
        half2 oh0 = __floats2half2_rn(a[0], a[1]);
        half2 oh1 = __floats2half2_rn(a[2], a[3]);
        half2 oh2 = __floats2half2_rn(a[4], a[5]);
        half2 oh3 = __floats2half2_rn(a[6], a[7]);
        int4 ov;
        ov.x = *reinterpret_cast<int*>(&oh0);
        ov.y = *reinterpret_cast<int*>(&oh1);
        ov.z = *reinterpret_cast<int*>(&oh2);
        ov.w = *reinterpret_cast<int*>(&oh3);
        reinterpret_cast<int4*>(g_X1h)[n * 8 + cg] = ov;
    }
    __syncthreads();
    if (threadIdx.x < H0) {
        int slot = (blockIdx.x & (BN_SLOTS - 1)) * H0 + threadIdx.x;
        atomicAdd(&g_bn_sum[slot], bs[threadIdx.x]);
        atomicAdd(&g_bn_sq[slot],  bq[threadIdx.x]);
    }
}

// ---------------------------------------------------------------------------
// kE: BN finalize (shuffle c0) + Z2[n] = Dv*(X1 @ (bn∘theta2)); 8 nodes/block
__global__ void __launch_bounds__(256)
kE_z2(const float* __restrict__ gamma, const float* __restrict__ beta,
      const float* __restrict__ th2,   const float* __restrict__ Dv) {
    __shared__ float scoef[H0];
    __shared__ float sred[H0];
    __shared__ float sc0s;
    int t = threadIdx.x;
    int warp = t >> 5, lane = t & 31;
    if (t < H0) {
        float s = 0.0f, q = 0.0f;
        #pragma unroll
        for (int j = 0; j < BN_SLOTS; j++) {
            s += g_bn_sum[j * H0 + t];
            q += g_bn_sq [j * H0 + t];
        }
        float mu   = s * (1.0f / NN);
        float var  = q * (1.0f / NN) - mu * mu;
        float rstd = rsqrtf(var + BN_EPS);
        float scale = rstd * __ldg(&gamma[t]);
        float shift = __ldg(&beta[t]) - mu * scale;
        float th = __ldg(&th2[t]);
        scoef[t] = scale * th;
        sred[t]  = shift * th;
    }
    __syncthreads();
    if (warp == 0) {
        float r = sred[lane] + sred[lane + 32];
        #pragma unroll
        for (int off = 16; off > 0; off >>= 1)
            r += __shfl_xor_sync(FULL, r, off);
        if (lane == 0) sc0s = r;
    }
    __syncthreads();
    float sc0 = sc0s;

    int n = blockIdx.x * 8 + warp;
    const half2*  Xh = reinterpret_cast<const half2*>(g_X1h);
    const float2* C2 = reinterpret_cast<const float2*>(scoef);
    float2 c = C2[lane];
    float2 x = __half22float2(Xh[n * 32 + lane]);
    float v = x.x * c.x + x.y * c.y;
    #pragma unroll
    for (int off = 16; off > 0; off >>= 1)
        v += __shfl_xor_sync(FULL, v, off);
    if (lane == 0) g_Z2[n] = __ldg(&Dv[n]) * (v + sc0);
}

// ---------------------------------------------------------------------------
// kF: M2[e] = WDe[e] * sum_{n in col(e)} Z2[n]   (warp per edge)
__global__ void __launch_bounds__(256) kF_edge2() {
    int t = blockIdx.x * blockDim.x + threadIdx.x;
    int e = t >> 5, lane = t & 31;
    int cnt = min(g_col_cnt[e], COL_CAP);
    const int* lst = &g_col_idx[e * COL_CAP];
    float a = 0.0f;
    for (int i = lane; i < cnt; i += 32) a += g_Z2[__ldg(&lst[i])];
    #pragma unroll
    for (int off = 16; off > 0; off >>= 1)
        a += __shfl_xor_sync(FULL, a, off);
    if (lane == 0) g_M2[e] = a * g_WDe[e];
}

// ---------------------------------------------------------------------------
// kG: out = sigmoid(Dv * row-gather(M2)) + restore zero-invariants
__global__ void __launch_bounds__(256)
kG_out(const float* __restrict__ Dv, float* __restrict__ out) {
    int t = blockIdx.x * blockDim.x + threadIdx.x;
    if (t < EE) g_col_cnt[t] = 0;
    if (t < BN_SLOTS * H0) { g_bn_sum[t] = 0.0f; g_bn_sq[t] = 0.0f; }
    int n = t >> 5, lane = t & 31;
    int cnt = min(g_row_cnt[n], ROW_CAP);
    const int* lst = &g_row_idx[n * ROW_CAP];
    float a = 0.0f;
    for (int i = lane; i < cnt; i += 32) a += g_M2[__ldg(&lst[i])];
    #pragma unroll
    for (int off = 16; off > 0; off >>= 1)
        a += __shfl_xor_sync(FULL, a, off);
    if (lane == 0) {
        float x = __ldg(&Dv[n]) * a;
        out[n] = 1.0f / (1.0f + __expf(-x));
        g_row_cnt[n] = 0;
    }
}

extern "C" void kernel_launch(void* const* d_in, const int* in_sizes, int n_in,
                              void* d_out, int out_size) {
    const float* X     = (const float*)d_in[0];
    const float* Dv    = (const float*)d_in[1];
    const float* De    = (const float*)d_in[2];
    const float* Hm    = (const float*)d_in[3];
    const float* W     = (const float*)d_in[4];
    const float* th1   = (const float*)d_in[5];
    const float* th2   = (const float*)d_in[6];
    const float* gamma = (const float*)d_in[7];
    const float* beta  = (const float*)d_in[8];
    float* out = (float*)d_out;

    kAB<<<GEMM_BLKS + SCAN_BLKS, 256>>>(X, th1, Dv, Hm, W, De);
    kC_edge<<<EE / 4, 256>>>();
    kD_node<<<NN / 8, 256>>>(Dv);
    kE_z2  <<<NN / 8, 256>>>(gamma, beta, th2, Dv);
    kF_edge2<<<EE / 8, 256>>>();
    kG_out <<<NN / 8, 256>>>(Dv, out);
}